// round 13
// baseline (speedup 1.0000x reference)
#include <cuda_runtime.h>
#include <cuda_fp16.h>
#include <math.h>
#include <stdint.h>

// Problem constants
#define NQ     12
#define DIMN   4096
#define HALFN  2048
#define NBATCH 2048
#define MROWS  (2 * NBATCH)   // stacked re/im rows = 4096
#define GK     4096           // GEMM K

// ---------------------------------------------------------------------------
// Scratch (__device__ globals per harness rules)
// All GEMM operands plain fp16 (ulp 2^-11; 8x tighter than bf16 — fixes the
// R12 precision regression at identical speed). fp32 accumulation.
// ---------------------------------------------------------------------------
__device__ __half g_Ah[(size_t)MROWS * DIMN];   // V, later gated W
__device__ __half g_Eh[(size_t)DIMN * DIMN];
__device__ __half g_Gh[(size_t)HALFN * DIMN];   // G = r00*Etop + r01*Ebot
__device__ float g_W[(size_t)MROWS * DIMN];     // GEMM1 output (fp32)
__device__ float g_gates[NQ * 8];

// ---------------------------------------------------------------------------
// prep: per-qubit gate matrices  mats[q] = Rx(w[3+q]) @ Rz(w[15+q])
// ---------------------------------------------------------------------------
__global__ void prep_kernel(const float* __restrict__ w) {
    int q = threadIdx.x;
    if (q < NQ) {
        float tx = 0.5f * w[3 + q];
        float tz = 0.5f * w[3 + NQ + q];
        float s, c, sz, cz;
        sincosf(tx, &s, &c);
        sincosf(tz, &sz, &cz);
        float* m = g_gates + q * 8;
        m[0] =  c * cz;  m[1] = -c * sz;
        m[2] =  s * sz;  m[3] = -s * cz;
        m[4] = -s * sz;  m[5] = -s * cz;
        m[6] =  c * cz;  m[7] =  c * sz;
    }
}

// ---------------------------------------------------------------------------
// split_EG: one pass over E producing Eh (fp16) and Gh (fp16, folded final rot)
// ---------------------------------------------------------------------------
__global__ __launch_bounds__(256) void split_EG(const float* __restrict__ E,
                                                const float* __restrict__ w) {
    float th  = 0.5f * (w[0] + w[1] + w[2]);
    float r00 = cosf(th);
    float r01 = -sinf(th);
    size_t i = (size_t)blockIdx.x * blockDim.x + threadIdx.x;   // float4 idx in top half
    const size_t HOFF4 = (size_t)HALFN * DIMN / 4;
    const float4* E4 = (const float4*)E;
    float4 a = E4[i];
    float4 b = E4[i + HOFF4];

    __half2* Eh2 = (__half2*)g_Eh;
    __half2* Gh2 = (__half2*)g_Gh;

    float va[4] = {a.x, a.y, a.z, a.w};
    float vb[4] = {b.x, b.y, b.z, b.w};
    __half eh[8], gh[4];
    #pragma unroll
    for (int k = 0; k < 4; ++k) {
        eh[k]     = __float2half(va[k]);
        eh[4 + k] = __float2half(vb[k]);
        gh[k]     = __float2half(r00 * va[k] + r01 * vb[k]);
    }
    size_t t2 = 2 * i;
    size_t b2 = 2 * (i + HOFF4);
    Eh2[t2]     = __halves2half2(eh[0], eh[1]);
    Eh2[t2 + 1] = __halves2half2(eh[2], eh[3]);
    Eh2[b2]     = __halves2half2(eh[4], eh[5]);
    Eh2[b2 + 1] = __halves2half2(eh[6], eh[7]);
    Gh2[t2]     = __halves2half2(gh[0], gh[1]);
    Gh2[t2 + 1] = __halves2half2(gh[2], gh[3]);
}

// ---------------------------------------------------------------------------
// encode: writes plain fp16 state
// ---------------------------------------------------------------------------
__global__ __launch_bounds__(256) void encode_kernel(const float* __restrict__ inputs) {
    __shared__ float ar[NQ], ai[NQ], br[NQ], bi[NQ];
    const int b = blockIdx.x;
    if (threadIdx.x < NQ) {
        float x = inputs[b * NQ + threadIdx.x];
        float sy, cy, sz, cz;
        sincosf(0.5f * x, &sy, &cy);
        sincosf(0.5f * x * x, &sz, &cz);
        ar[threadIdx.x] = cy * cz;  ai[threadIdx.x] = -cy * sz;
        br[threadIdx.x] = sy * cz;  bi[threadIdx.x] =  sy * sz;
    }
    __syncthreads();
    for (int j = threadIdx.x; j < DIMN; j += blockDim.x) {
        float pr = 1.f, pi = 0.f;
        #pragma unroll
        for (int q = 0; q < NQ; ++q) {
            int bit = (j >> (NQ - 1 - q)) & 1;
            float cr = bit ? br[q] : ar[q];
            float ci = bit ? bi[q] : ai[q];
            float nr = pr * cr - pi * ci;
            float ni = pr * ci + pi * cr;
            pr = nr; pi = ni;
        }
        g_Ah[(size_t)b * DIMN + j]            = __float2half(pr);
        g_Ah[(size_t)(NBATCH + b) * DIMN + j] = __float2half(pi);
    }
}

// ---------------------------------------------------------------------------
// Plain-fp16 NT GEMM (mma.sync + ldmatrix), persistent tile loop:
//   C[M,N] = A[M,K] * B[N,K]^T   (single term, fp32 accum)
// CTA tile 128x128, BK=32, 5-stage cp.async ring, 8 warps (warp 64x32),
// 2 CTAs/SM (80KB smem each). One __syncthreads per chunk.
// which==1 (GEMM2): fused |.|^2 row-reduction epilogue -> atomicAdd(out).
// ---------------------------------------------------------------------------
#define BM 128
#define BN 128
#define BKC 32
#define STAGES 5
#define OAH 0
#define OBH 8192
#define STG 16384
#define DSMEM (STAGES * STG)   // 81920

__device__ __forceinline__ uint32_t smem_u32(const void* p) {
    return (uint32_t)__cvta_generic_to_shared(p);
}
__device__ __forceinline__ void cpa16u(uint32_t s, const void* g) {
    asm volatile("cp.async.cg.shared.global [%0], [%1], 16;" :: "r"(s), "l"(g));
}
__device__ __forceinline__ void ldsm4(uint32_t& r0, uint32_t& r1, uint32_t& r2,
                                      uint32_t& r3, uint32_t a) {
    asm volatile("ldmatrix.sync.aligned.m8n8.x4.shared.b16 {%0,%1,%2,%3}, [%4];"
                 : "=r"(r0), "=r"(r1), "=r"(r2), "=r"(r3) : "r"(a));
}
__device__ __forceinline__ void mma16(float c[4], const uint32_t a[4], const uint32_t b[2]) {
    asm volatile(
        "mma.sync.aligned.m16n8k16.row.col.f32.f16.f16.f32 "
        "{%0,%1,%2,%3}, {%4,%5,%6,%7}, {%8,%9}, {%0,%1,%2,%3};\n"
        : "+f"(c[0]), "+f"(c[1]), "+f"(c[2]), "+f"(c[3])
        : "r"(a[0]), "r"(a[1]), "r"(a[2]), "r"(a[3]), "r"(b[0]), "r"(b[1]));
}

// swizzled byte offset within a 64B-row tile
__device__ __forceinline__ uint32_t swz(int row, int chunk) {
    return (uint32_t)row * 64u + (uint32_t)((chunk ^ ((row >> 1) & 3)) << 4);
}

// load one BK=32 chunk (A, B tiles) into a stage
__device__ __forceinline__ void load_chunk(uint32_t sbase,
    const __half* __restrict__ Ah, const __half* __restrict__ Bh,
    size_t aoff, size_t boff, int k0, int tid)
{
    const int r = tid >> 2;        // 0..63
    const int j = tid & 3;         // 16B chunk
    #pragma unroll
    for (int i = 0; i < 2; ++i) {
        int row = r + 64 * i;
        uint32_t so = swz(row, j);
        size_t go = aoff + (size_t)row * GK + k0 + j * 8;
        cpa16u(sbase + OAH + so, Ah + go);
        size_t gob = boff + (size_t)row * GK + k0 + j * 8;
        cpa16u(sbase + OBH + so, Bh + gob);
    }
}

__global__ void __launch_bounds__(256, 2)
gemm_split(int which, float* __restrict__ gout) {
    extern __shared__ char dsm[];
    const uint32_t sb = smem_u32(dsm);
    const int tid  = threadIdx.x;
    const int warp = tid >> 5;
    const int lane = tid & 31;
    const int wm = (warp & 1) * 64;
    const int wn = (warp >> 1) * 32;

    const __half* Ah = g_Ah;
    const __half* Bh = which ? g_Gh : g_Eh;
    const int Ntot = which ? HALFN : DIMN;
    const int nblk = Ntot / BN;
    const int ntiles = (MROWS / BM) * nblk;

    // ldmatrix thread->row mapping (tile-independent)
    const int q = lane >> 3;       // matrix index 0..3
    const int e = lane & 7;        // row within 8
    int arow[4]; uint32_t aox[4];
    #pragma unroll
    for (int mt = 0; mt < 4; ++mt) {
        arow[mt] = wm + mt * 16 + e + (q & 1) * 8;
        aox[mt]  = (uint32_t)arow[mt] * 64u;
    }
    const int acs = q >> 1;        // chunk add for A mats
    int brow[2];
    #pragma unroll
    for (int p = 0; p < 2; ++p)
        brow[p] = wn + p * 16 + e + (q >> 1) * 8;
    const int bcs = q & 1;         // chunk add for B mats

    const int g  = lane >> 2;
    const int t4 = lane & 3;
    const int nk = GK / BKC;       // 128

    for (int t = blockIdx.x; t < ntiles; t += gridDim.x) {
        const int mb = t / nblk;
        const int nb = t - mb * nblk;
        const size_t aoff = (size_t)mb * BM * GK;
        const size_t boff = (size_t)nb * BN * GK;

        float acc[4][4][4];
        #pragma unroll
        for (int i = 0; i < 4; ++i)
            #pragma unroll
            for (int jj = 0; jj < 4; ++jj)
                #pragma unroll
                for (int k = 0; k < 4; ++k) acc[i][jj][k] = 0.f;

        // prologue: chunks 0..3 -> stages 0..3
        #pragma unroll
        for (int s = 0; s < 4; ++s) {
            load_chunk(sb + s * STG, Ah, Bh, aoff, boff, s * BKC, tid);
            asm volatile("cp.async.commit_group;" ::: "memory");
        }

        int stage = 0;
        for (int it = 0; it < nk; ++it) {
            if (it < nk - 3)       asm volatile("cp.async.wait_group 3;" ::: "memory");
            else if (it == nk - 3) asm volatile("cp.async.wait_group 2;" ::: "memory");
            else if (it == nk - 2) asm volatile("cp.async.wait_group 1;" ::: "memory");
            else                   asm volatile("cp.async.wait_group 0;" ::: "memory");
            __syncthreads();

            if (it + 4 < nk) {
                int ns = stage + 4; if (ns >= STAGES) ns -= STAGES;
                load_chunk(sb + ns * STG, Ah, Bh, aoff, boff,
                           (it + 4) * BKC, tid);
                asm volatile("cp.async.commit_group;" ::: "memory");
            }

            const uint32_t stg = sb + (uint32_t)stage * STG;
            #pragma unroll
            for (int ks = 0; ks < 2; ++ks) {
                const int c = 2 * ks;
                uint32_t afh[4][4], bfh[2][4];
                #pragma unroll
                for (int mt = 0; mt < 4; ++mt) {
                    uint32_t sx = (uint32_t)(((c + acs) ^ ((arow[mt] >> 1) & 3)) << 4);
                    ldsm4(afh[mt][0], afh[mt][1], afh[mt][2], afh[mt][3],
                          stg + OAH + aox[mt] + sx);
                }
                #pragma unroll
                for (int p = 0; p < 2; ++p) {
                    uint32_t sx = swz(brow[p], c + bcs);
                    ldsm4(bfh[p][0], bfh[p][1], bfh[p][2], bfh[p][3], stg + OBH + sx);
                }
                #pragma unroll
                for (int mt = 0; mt < 4; ++mt)
                    #pragma unroll
                    for (int p = 0; p < 2; ++p)
                        #pragma unroll
                        for (int h = 0; h < 2; ++h)
                            mma16(acc[mt][2 * p + h], afh[mt], &bfh[p][2 * h]);
            }
            if (++stage >= STAGES) stage = 0;
        }

        if (which == 0) {
            // GEMM1 epilogue: store W
            #pragma unroll
            for (int mt = 0; mt < 4; ++mt) {
                int row = mb * BM + wm + mt * 16 + g;
                #pragma unroll
                for (int nt = 0; nt < 4; ++nt) {
                    int col = nb * BN + wn + nt * 8 + 2 * t4;
                    float2 v0 = make_float2(acc[mt][nt][0], acc[mt][nt][1]);
                    float2 v1 = make_float2(acc[mt][nt][2], acc[mt][nt][3]);
                    *(float2*)&g_W[(size_t)row * Ntot + col]       = v0;
                    *(float2*)&g_W[(size_t)(row + 8) * Ntot + col] = v1;
                }
            }
        } else {
            // GEMM2 epilogue: fused |.|^2 row reduction -> out[row mod 2048]
            #pragma unroll
            for (int mt = 0; mt < 4; ++mt) {
                float s0 = 0.f, s1 = 0.f;
                #pragma unroll
                for (int nt = 0; nt < 4; ++nt) {
                    s0 += acc[mt][nt][0] * acc[mt][nt][0]
                        + acc[mt][nt][1] * acc[mt][nt][1];
                    s1 += acc[mt][nt][2] * acc[mt][nt][2]
                        + acc[mt][nt][3] * acc[mt][nt][3];
                }
                s0 += __shfl_xor_sync(0xffffffffu, s0, 1);
                s0 += __shfl_xor_sync(0xffffffffu, s0, 2);
                s1 += __shfl_xor_sync(0xffffffffu, s1, 1);
                s1 += __shfl_xor_sync(0xffffffffu, s1, 2);
                if (t4 == 0) {
                    int row = mb * BM + wm + mt * 16 + g;
                    atomicAdd(&gout[row & (NBATCH - 1)], s0);
                    atomicAdd(&gout[(row + 8) & (NBATCH - 1)], s1);
                }
            }
        }
        // protect smem stages from next tile's prologue
        __syncthreads();
    }
}

// ---------------------------------------------------------------------------
// gate sweep: apply 12 complex 2x2 gates per batch row in smem, write fp16
// ---------------------------------------------------------------------------
__global__ __launch_bounds__(256) void gate_kernel() {
    __shared__ float wr[DIMN];
    __shared__ float wi[DIMN];
    const int b = blockIdx.x;
    const float* Wr = g_W + (size_t)b * DIMN;
    const float* Wi = g_W + (size_t)(NBATCH + b) * DIMN;

    for (int j = threadIdx.x * 4; j < DIMN; j += blockDim.x * 4) {
        *(float4*)&wr[j] = *(const float4*)&Wr[j];
        *(float4*)&wi[j] = *(const float4*)&Wi[j];
    }
    __syncthreads();

    #pragma unroll 1
    for (int q = 0; q < NQ; ++q) {
        const float* m = g_gates + q * 8;
        float m00r = m[0], m00i = m[1], m01r = m[2], m01i = m[3];
        float m10r = m[4], m10i = m[5], m11r = m[6], m11i = m[7];
        int p  = NQ - 1 - q;
        int st = 1 << p;
        for (int t = threadIdx.x; t < HALFN; t += blockDim.x) {
            int j0 = ((t >> p) << (p + 1)) | (t & (st - 1));
            int j1 = j0 + st;
            float w0r = wr[j0], w0i = wi[j0];
            float w1r = wr[j1], w1i = wi[j1];
            wr[j0] = m00r * w0r - m00i * w0i + m01r * w1r - m01i * w1i;
            wi[j0] = m00r * w0i + m00i * w0r + m01r * w1i + m01i * w1r;
            wr[j1] = m10r * w0r - m10i * w0i + m11r * w1r - m11i * w1i;
            wi[j1] = m10r * w0i + m10i * w0r + m11r * w1i + m11i * w1r;
        }
        __syncthreads();
    }

    for (int j = threadIdx.x; j < DIMN; j += blockDim.x) {
        g_Ah[(size_t)b * DIMN + j]            = __float2half(wr[j]);
        g_Ah[(size_t)(NBATCH + b) * DIMN + j] = __float2half(wi[j]);
    }
}

// ---------------------------------------------------------------------------
extern "C" void kernel_launch(void* const* d_in, const int* in_sizes, int n_in,
                              void* d_out, int out_size) {
    const float* inputs = (const float*)d_in[0];   // [2048,12]
    const float* weight = (const float*)d_in[1];   // [27]
    const float* E      = (const float*)d_in[2];   // [4096,4096]
    float* out          = (float*)d_out;           // [2048]

    cudaFuncSetAttribute(gemm_split, cudaFuncAttributeMaxDynamicSharedMemorySize,
                         DSMEM);
    int nsm = 148;
    cudaDeviceGetAttribute(&nsm, cudaDevAttrMultiProcessorCount, 0);
    const int pgrid = 2 * nsm;     // persistent grid: 2 CTAs per SM

    cudaMemsetAsync(out, 0, (size_t)out_size * sizeof(float));
    prep_kernel<<<1, 32>>>(weight);
    split_EG<<<(HALFN * DIMN / 4) / 256, 256>>>(E, weight);
    encode_kernel<<<NBATCH, 256>>>(inputs);

    gemm_split<<<pgrid, 256, DSMEM>>>(0, out);
    gate_kernel<<<NBATCH, 256>>>();
    gemm_split<<<pgrid, 256, DSMEM>>>(1, out);
}

// round 14
// speedup vs baseline: 1.1802x; 1.1802x over previous
#include <cuda_runtime.h>
#include <cuda_fp16.h>
#include <math.h>
#include <stdint.h>

// Problem constants
#define NQ     12
#define DIMN   4096
#define HALFN  2048
#define NBATCH 2048
#define MROWS  (2 * NBATCH)   // stacked re/im rows = 4096
#define GK     4096           // GEMM K

// ---------------------------------------------------------------------------
// Scratch (__device__ globals per harness rules)
// ---------------------------------------------------------------------------
__device__ __half g_Ah[(size_t)MROWS * DIMN];   // V, later gated W
__device__ __half g_Eh[(size_t)DIMN * DIMN];
__device__ __half g_Gh[(size_t)HALFN * DIMN];   // G = r00*Etop + r01*Ebot
__device__ float g_W[(size_t)MROWS * DIMN];     // GEMM1 output (fp32)
__device__ float g_gates[NQ * 8];

// ---------------------------------------------------------------------------
// prep: per-qubit gate matrices  mats[q] = Rx(w[3+q]) @ Rz(w[15+q])
// ---------------------------------------------------------------------------
__global__ void prep_kernel(const float* __restrict__ w) {
    int q = threadIdx.x;
    if (q < NQ) {
        float tx = 0.5f * w[3 + q];
        float tz = 0.5f * w[3 + NQ + q];
        float s, c, sz, cz;
        sincosf(tx, &s, &c);
        sincosf(tz, &sz, &cz);
        float* m = g_gates + q * 8;
        m[0] =  c * cz;  m[1] = -c * sz;
        m[2] =  s * sz;  m[3] = -s * cz;
        m[4] = -s * sz;  m[5] = -s * cz;
        m[6] =  c * cz;  m[7] =  c * sz;
    }
}

// ---------------------------------------------------------------------------
// split_EG: one pass over E producing Eh (fp16) and Gh (fp16, folded final rot)
// ---------------------------------------------------------------------------
__global__ __launch_bounds__(256) void split_EG(const float* __restrict__ E,
                                                const float* __restrict__ w) {
    float th  = 0.5f * (w[0] + w[1] + w[2]);
    float r00 = cosf(th);
    float r01 = -sinf(th);
    size_t i = (size_t)blockIdx.x * blockDim.x + threadIdx.x;   // float4 idx in top half
    const size_t HOFF4 = (size_t)HALFN * DIMN / 4;
    const float4* E4 = (const float4*)E;
    float4 a = E4[i];
    float4 b = E4[i + HOFF4];

    __half2* Eh2 = (__half2*)g_Eh;
    __half2* Gh2 = (__half2*)g_Gh;

    float va[4] = {a.x, a.y, a.z, a.w};
    float vb[4] = {b.x, b.y, b.z, b.w};
    __half eh[8], gh[4];
    #pragma unroll
    for (int k = 0; k < 4; ++k) {
        eh[k]     = __float2half(va[k]);
        eh[4 + k] = __float2half(vb[k]);
        gh[k]     = __float2half(r00 * va[k] + r01 * vb[k]);
    }
    size_t t2 = 2 * i;
    size_t b2 = 2 * (i + HOFF4);
    Eh2[t2]     = __halves2half2(eh[0], eh[1]);
    Eh2[t2 + 1] = __halves2half2(eh[2], eh[3]);
    Eh2[b2]     = __halves2half2(eh[4], eh[5]);
    Eh2[b2 + 1] = __halves2half2(eh[6], eh[7]);
    Gh2[t2]     = __halves2half2(gh[0], gh[1]);
    Gh2[t2 + 1] = __halves2half2(gh[2], gh[3]);
}

// ---------------------------------------------------------------------------
// encode: writes plain fp16 state
// ---------------------------------------------------------------------------
__global__ __launch_bounds__(256) void encode_kernel(const float* __restrict__ inputs) {
    __shared__ float ar[NQ], ai[NQ], br[NQ], bi[NQ];
    const int b = blockIdx.x;
    if (threadIdx.x < NQ) {
        float x = inputs[b * NQ + threadIdx.x];
        float sy, cy, sz, cz;
        sincosf(0.5f * x, &sy, &cy);
        sincosf(0.5f * x * x, &sz, &cz);
        ar[threadIdx.x] = cy * cz;  ai[threadIdx.x] = -cy * sz;
        br[threadIdx.x] = sy * cz;  bi[threadIdx.x] =  sy * sz;
    }
    __syncthreads();
    for (int j = threadIdx.x; j < DIMN; j += blockDim.x) {
        float pr = 1.f, pi = 0.f;
        #pragma unroll
        for (int q = 0; q < NQ; ++q) {
            int bit = (j >> (NQ - 1 - q)) & 1;
            float cr = bit ? br[q] : ar[q];
            float ci = bit ? bi[q] : ai[q];
            float nr = pr * cr - pi * ci;
            float ni = pr * ci + pi * cr;
            pr = nr; pi = ni;
        }
        g_Ah[(size_t)b * DIMN + j]            = __float2half(pr);
        g_Ah[(size_t)(NBATCH + b) * DIMN + j] = __float2half(pi);
    }
}

// ---------------------------------------------------------------------------
// Plain-fp16 NT GEMM (mma.sync + ldmatrix), persistent tile loop:
//   C[M,N] = A[M,K] * B[N,K]^T   (fp32 accum)
// CTA tile 128x128, 4 warps (128 threads), WARP TILE 64x64 (smem-traffic
// relief: 16 MAC/B vs 10.9), BK=32, 5-stage cp.async ring, 2 CTAs/SM.
// ldsm swizzle offsets fully precomputed outside the mainloop.
// which==1 (GEMM2): fused |.|^2 row-reduction epilogue -> atomicAdd(out).
// ---------------------------------------------------------------------------
#define BM 128
#define BN 128
#define BKC 32
#define STAGES 5
#define OAH 0
#define OBH 8192
#define STG 16384
#define DSMEM (STAGES * STG)   // 81920
#define NTHR 128

__device__ __forceinline__ uint32_t smem_u32(const void* p) {
    return (uint32_t)__cvta_generic_to_shared(p);
}
__device__ __forceinline__ void cpa16u(uint32_t s, const void* g) {
    asm volatile("cp.async.cg.shared.global [%0], [%1], 16;" :: "r"(s), "l"(g));
}
__device__ __forceinline__ void ldsm4(uint32_t& r0, uint32_t& r1, uint32_t& r2,
                                      uint32_t& r3, uint32_t a) {
    asm volatile("ldmatrix.sync.aligned.m8n8.x4.shared.b16 {%0,%1,%2,%3}, [%4];"
                 : "=r"(r0), "=r"(r1), "=r"(r2), "=r"(r3) : "r"(a));
}
__device__ __forceinline__ void mma16(float c[4], const uint32_t a[4], const uint32_t b[2]) {
    asm volatile(
        "mma.sync.aligned.m16n8k16.row.col.f32.f16.f16.f32 "
        "{%0,%1,%2,%3}, {%4,%5,%6,%7}, {%8,%9}, {%0,%1,%2,%3};\n"
        : "+f"(c[0]), "+f"(c[1]), "+f"(c[2]), "+f"(c[3])
        : "r"(a[0]), "r"(a[1]), "r"(a[2]), "r"(a[3]), "r"(b[0]), "r"(b[1]));
}

// swizzled byte offset within a 64B-row tile
__device__ __forceinline__ uint32_t swz(int row, int chunk) {
    return (uint32_t)row * 64u + (uint32_t)((chunk ^ ((row >> 1) & 3)) << 4);
}

// load one BK=32 chunk (A, B tiles: 128 rows each) with 128 threads
__device__ __forceinline__ void load_chunk(uint32_t sbase,
    const __half* __restrict__ Ah, const __half* __restrict__ Bh,
    size_t aoff, size_t boff, int k0, int tid)
{
    const int r = tid >> 2;        // 0..31
    const int j = tid & 3;         // 16B chunk
    #pragma unroll
    for (int i = 0; i < 4; ++i) {
        int row = r + 32 * i;
        uint32_t so = swz(row, j);
        size_t go = aoff + (size_t)row * GK + k0 + j * 8;
        cpa16u(sbase + OAH + so, Ah + go);
        size_t gob = boff + (size_t)row * GK + k0 + j * 8;
        cpa16u(sbase + OBH + so, Bh + gob);
    }
}

__global__ void __launch_bounds__(NTHR, 2)
gemm_split(int which, float* __restrict__ gout) {
    extern __shared__ char dsm[];
    const uint32_t sb = smem_u32(dsm);
    const int tid  = threadIdx.x;
    const int warp = tid >> 5;
    const int lane = tid & 31;
    const int wm = (warp & 1) * 64;
    const int wn = (warp >> 1) * 64;

    const __half* Ah = g_Ah;
    const __half* Bh = which ? g_Gh : g_Eh;
    const int Ntot = which ? HALFN : DIMN;
    const int nblk = Ntot / BN;
    const int ntiles = (MROWS / BM) * nblk;

    // ldmatrix thread->row mapping; precompute ALL swizzled offsets (per ks)
    const int q = lane >> 3;       // matrix index 0..3
    const int e = lane & 7;        // row within 8
    const int acs = q >> 1;
    const int bcs = q & 1;
    uint32_t aofs[2][4], bofs[2][4];
    #pragma unroll
    for (int ks = 0; ks < 2; ++ks) {
        #pragma unroll
        for (int mt = 0; mt < 4; ++mt) {
            int row = wm + mt * 16 + e + (q & 1) * 8;
            aofs[ks][mt] = OAH + swz(row, 2 * ks + acs);
        }
        #pragma unroll
        for (int p = 0; p < 4; ++p) {
            int row = wn + p * 16 + e + (q >> 1) * 8;
            bofs[ks][p] = OBH + swz(row, 2 * ks + bcs);
        }
    }

    const int g  = lane >> 2;
    const int t4 = lane & 3;
    const int nk = GK / BKC;       // 128

    for (int t = blockIdx.x; t < ntiles; t += gridDim.x) {
        const int mb = t / nblk;
        const int nb = t - mb * nblk;
        const size_t aoff = (size_t)mb * BM * GK;
        const size_t boff = (size_t)nb * BN * GK;

        float acc[4][8][4];
        #pragma unroll
        for (int i = 0; i < 4; ++i)
            #pragma unroll
            for (int jj = 0; jj < 8; ++jj)
                #pragma unroll
                for (int k = 0; k < 4; ++k) acc[i][jj][k] = 0.f;

        // prologue: chunks 0..3 -> stages 0..3
        #pragma unroll
        for (int s = 0; s < 4; ++s) {
            load_chunk(sb + s * STG, Ah, Bh, aoff, boff, s * BKC, tid);
            asm volatile("cp.async.commit_group;" ::: "memory");
        }

        int stage = 0;
        for (int it = 0; it < nk; ++it) {
            if (it < nk - 3)       asm volatile("cp.async.wait_group 3;" ::: "memory");
            else if (it == nk - 3) asm volatile("cp.async.wait_group 2;" ::: "memory");
            else if (it == nk - 2) asm volatile("cp.async.wait_group 1;" ::: "memory");
            else                   asm volatile("cp.async.wait_group 0;" ::: "memory");
            __syncthreads();

            if (it + 4 < nk) {
                int ns = stage + 4; if (ns >= STAGES) ns -= STAGES;
                load_chunk(sb + ns * STG, Ah, Bh, aoff, boff,
                           (it + 4) * BKC, tid);
                asm volatile("cp.async.commit_group;" ::: "memory");
            }

            const uint32_t stg = sb + (uint32_t)stage * STG;
            #pragma unroll
            for (int ks = 0; ks < 2; ++ks) {
                uint32_t afh[4][4], bfh[4][4];
                #pragma unroll
                for (int mt = 0; mt < 4; ++mt)
                    ldsm4(afh[mt][0], afh[mt][1], afh[mt][2], afh[mt][3],
                          stg + aofs[ks][mt]);
                #pragma unroll
                for (int p = 0; p < 4; ++p)
                    ldsm4(bfh[p][0], bfh[p][1], bfh[p][2], bfh[p][3],
                          stg + bofs[ks][p]);
                #pragma unroll
                for (int mt = 0; mt < 4; ++mt)
                    #pragma unroll
                    for (int p = 0; p < 4; ++p)
                        #pragma unroll
                        for (int h = 0; h < 2; ++h)
                            mma16(acc[mt][2 * p + h], afh[mt], &bfh[p][2 * h]);
            }
            if (++stage >= STAGES) stage = 0;
        }

        if (which == 0) {
            // GEMM1 epilogue: store W
            #pragma unroll
            for (int mt = 0; mt < 4; ++mt) {
                int row = mb * BM + wm + mt * 16 + g;
                #pragma unroll
                for (int nt = 0; nt < 8; ++nt) {
                    int col = nb * BN + wn + nt * 8 + 2 * t4;
                    float2 v0 = make_float2(acc[mt][nt][0], acc[mt][nt][1]);
                    float2 v1 = make_float2(acc[mt][nt][2], acc[mt][nt][3]);
                    *(float2*)&g_W[(size_t)row * Ntot + col]       = v0;
                    *(float2*)&g_W[(size_t)(row + 8) * Ntot + col] = v1;
                }
            }
        } else {
            // GEMM2 epilogue: fused |.|^2 row reduction -> out[row mod 2048]
            #pragma unroll
            for (int mt = 0; mt < 4; ++mt) {
                float s0 = 0.f, s1 = 0.f;
                #pragma unroll
                for (int nt = 0; nt < 8; ++nt) {
                    s0 += acc[mt][nt][0] * acc[mt][nt][0]
                        + acc[mt][nt][1] * acc[mt][nt][1];
                    s1 += acc[mt][nt][2] * acc[mt][nt][2]
                        + acc[mt][nt][3] * acc[mt][nt][3];
                }
                s0 += __shfl_xor_sync(0xffffffffu, s0, 1);
                s0 += __shfl_xor_sync(0xffffffffu, s0, 2);
                s1 += __shfl_xor_sync(0xffffffffu, s1, 1);
                s1 += __shfl_xor_sync(0xffffffffu, s1, 2);
                if (t4 == 0) {
                    int row = mb * BM + wm + mt * 16 + g;
                    atomicAdd(&gout[row & (NBATCH - 1)], s0);
                    atomicAdd(&gout[(row + 8) & (NBATCH - 1)], s1);
                }
            }
        }
        // protect smem stages from next tile's prologue
        __syncthreads();
    }
}

// ---------------------------------------------------------------------------
// gate sweep: apply 12 complex 2x2 gates per batch row in smem, write fp16
// ---------------------------------------------------------------------------
__global__ __launch_bounds__(256) void gate_kernel() {
    __shared__ float wr[DIMN];
    __shared__ float wi[DIMN];
    const int b = blockIdx.x;
    const float* Wr = g_W + (size_t)b * DIMN;
    const float* Wi = g_W + (size_t)(NBATCH + b) * DIMN;

    for (int j = threadIdx.x * 4; j < DIMN; j += blockDim.x * 4) {
        *(float4*)&wr[j] = *(const float4*)&Wr[j];
        *(float4*)&wi[j] = *(const float4*)&Wi[j];
    }
    __syncthreads();

    #pragma unroll 1
    for (int q = 0; q < NQ; ++q) {
        const float* m = g_gates + q * 8;
        float m00r = m[0], m00i = m[1], m01r = m[2], m01i = m[3];
        float m10r = m[4], m10i = m[5], m11r = m[6], m11i = m[7];
        int p  = NQ - 1 - q;
        int st = 1 << p;
        for (int t = threadIdx.x; t < HALFN; t += blockDim.x) {
            int j0 = ((t >> p) << (p + 1)) | (t & (st - 1));
            int j1 = j0 + st;
            float w0r = wr[j0], w0i = wi[j0];
            float w1r = wr[j1], w1i = wi[j1];
            wr[j0] = m00r * w0r - m00i * w0i + m01r * w1r - m01i * w1i;
            wi[j0] = m00r * w0i + m00i * w0r + m01r * w1i + m01i * w1r;
            wr[j1] = m10r * w0r - m10i * w0i + m11r * w1r - m11i * w1i;
            wi[j1] = m10r * w0i + m10i * w0r + m11r * w1i + m11i * w1r;
        }
        __syncthreads();
    }

    for (int j = threadIdx.x; j < DIMN; j += blockDim.x) {
        g_Ah[(size_t)b * DIMN + j]            = __float2half(wr[j]);
        g_Ah[(size_t)(NBATCH + b) * DIMN + j] = __float2half(wi[j]);
    }
}

// ---------------------------------------------------------------------------
extern "C" void kernel_launch(void* const* d_in, const int* in_sizes, int n_in,
                              void* d_out, int out_size) {
    const float* inputs = (const float*)d_in[0];   // [2048,12]
    const float* weight = (const float*)d_in[1];   // [27]
    const float* E      = (const float*)d_in[2];   // [4096,4096]
    float* out          = (float*)d_out;           // [2048]

    cudaFuncSetAttribute(gemm_split, cudaFuncAttributeMaxDynamicSharedMemorySize,
                         DSMEM);
    int nsm = 148;
    cudaDeviceGetAttribute(&nsm, cudaDevAttrMultiProcessorCount, 0);
    const int pgrid = 2 * nsm;     // persistent grid: 2 CTAs per SM

    cudaMemsetAsync(out, 0, (size_t)out_size * sizeof(float));
    prep_kernel<<<1, 32>>>(weight);
    split_EG<<<(HALFN * DIMN / 4) / 256, 256>>>(E, weight);
    encode_kernel<<<NBATCH, 256>>>(inputs);

    gemm_split<<<pgrid, NTHR, DSMEM>>>(0, out);
    gate_kernel<<<NBATCH, 256>>>();
    gemm_split<<<pgrid, NTHR, DSMEM>>>(1, out);
}

// round 15
// speedup vs baseline: 1.1829x; 1.0023x over previous
#include <cuda_runtime.h>
#include <cuda_fp16.h>
#include <math.h>
#include <stdint.h>

// Problem constants
#define NQ     12
#define DIMN   4096
#define HALFN  2048
#define NBATCH 2048
#define MROWS  (2 * NBATCH)   // stacked re/im rows = 4096
#define GK     4096           // GEMM K

// ---------------------------------------------------------------------------
// Scratch (__device__ globals per harness rules)
// ---------------------------------------------------------------------------
__device__ __half g_Ah[(size_t)MROWS * DIMN];   // V, later gated W
__device__ __half g_Eh[(size_t)DIMN * DIMN];
__device__ __half g_Gh[(size_t)HALFN * DIMN];   // G = r00*Etop + r01*Ebot
__device__ float g_W[(size_t)MROWS * DIMN];     // GEMM1 output (fp32)
__device__ float g_gates[NQ * 8];

// ---------------------------------------------------------------------------
// prep: per-qubit gate matrices  mats[q] = Rx(w[3+q]) @ Rz(w[15+q])
// ---------------------------------------------------------------------------
__global__ void prep_kernel(const float* __restrict__ w) {
    int q = threadIdx.x;
    if (q < NQ) {
        float tx = 0.5f * w[3 + q];
        float tz = 0.5f * w[3 + NQ + q];
        float s, c, sz, cz;
        sincosf(tx, &s, &c);
        sincosf(tz, &sz, &cz);
        float* m = g_gates + q * 8;
        m[0] =  c * cz;  m[1] = -c * sz;
        m[2] =  s * sz;  m[3] = -s * cz;
        m[4] = -s * sz;  m[5] = -s * cz;
        m[6] =  c * cz;  m[7] =  c * sz;
    }
}

// ---------------------------------------------------------------------------
// split_EG: one pass over E producing Eh (fp16) and Gh (fp16, folded final rot)
// ---------------------------------------------------------------------------
__global__ __launch_bounds__(256) void split_EG(const float* __restrict__ E,
                                                const float* __restrict__ w) {
    float th  = 0.5f * (w[0] + w[1] + w[2]);
    float r00 = cosf(th);
    float r01 = -sinf(th);
    size_t i = (size_t)blockIdx.x * blockDim.x + threadIdx.x;   // float4 idx in top half
    const size_t HOFF4 = (size_t)HALFN * DIMN / 4;
    const float4* E4 = (const float4*)E;
    float4 a = E4[i];
    float4 b = E4[i + HOFF4];

    __half2* Eh2 = (__half2*)g_Eh;
    __half2* Gh2 = (__half2*)g_Gh;

    float va[4] = {a.x, a.y, a.z, a.w};
    float vb[4] = {b.x, b.y, b.z, b.w};
    __half eh[8], gh[4];
    #pragma unroll
    for (int k = 0; k < 4; ++k) {
        eh[k]     = __float2half(va[k]);
        eh[4 + k] = __float2half(vb[k]);
        gh[k]     = __float2half(r00 * va[k] + r01 * vb[k]);
    }
    size_t t2 = 2 * i;
    size_t b2 = 2 * (i + HOFF4);
    Eh2[t2]     = __halves2half2(eh[0], eh[1]);
    Eh2[t2 + 1] = __halves2half2(eh[2], eh[3]);
    Eh2[b2]     = __halves2half2(eh[4], eh[5]);
    Eh2[b2 + 1] = __halves2half2(eh[6], eh[7]);
    Gh2[t2]     = __halves2half2(gh[0], gh[1]);
    Gh2[t2 + 1] = __halves2half2(gh[2], gh[3]);
}

// ---------------------------------------------------------------------------
// encode: writes plain fp16 state
// ---------------------------------------------------------------------------
__global__ __launch_bounds__(256) void encode_kernel(const float* __restrict__ inputs) {
    __shared__ float ar[NQ], ai[NQ], br[NQ], bi[NQ];
    const int b = blockIdx.x;
    if (threadIdx.x < NQ) {
        float x = inputs[b * NQ + threadIdx.x];
        float sy, cy, sz, cz;
        sincosf(0.5f * x, &sy, &cy);
        sincosf(0.5f * x * x, &sz, &cz);
        ar[threadIdx.x] = cy * cz;  ai[threadIdx.x] = -cy * sz;
        br[threadIdx.x] = sy * cz;  bi[threadIdx.x] =  sy * sz;
    }
    __syncthreads();
    for (int j = threadIdx.x; j < DIMN; j += blockDim.x) {
        float pr = 1.f, pi = 0.f;
        #pragma unroll
        for (int q = 0; q < NQ; ++q) {
            int bit = (j >> (NQ - 1 - q)) & 1;
            float cr = bit ? br[q] : ar[q];
            float ci = bit ? bi[q] : ai[q];
            float nr = pr * cr - pi * ci;
            float ni = pr * ci + pi * cr;
            pr = nr; pi = ni;
        }
        g_Ah[(size_t)b * DIMN + j]            = __float2half(pr);
        g_Ah[(size_t)(NBATCH + b) * DIMN + j] = __float2half(pi);
    }
}

// ---------------------------------------------------------------------------
// Plain-fp16 NT GEMM (mma.sync + ldmatrix), persistent tile loop:
//   C[M,N] = A[M,K] * B[N,K]^T   (fp32 accum)
// CTA tile 128x128, 4 warps (128 threads), warp tile 64x64, BK=64 (halved
// barrier count vs BK=32), 3-stage cp.async ring (32KB stages), 2 CTAs/SM.
// SW128 swizzle (128B rows, chunk ^= row&7). All ldsm offsets precomputed.
// which==1 (GEMM2): fused |.|^2 row-reduction epilogue -> atomicAdd(out).
// ---------------------------------------------------------------------------
#define BM 128
#define BN 128
#define BKC 64
#define STAGES 3
#define OAH 0
#define OBH 16384
#define STG 32768
#define DSMEM (STAGES * STG)   // 98304
#define NTHR 128

__device__ __forceinline__ uint32_t smem_u32(const void* p) {
    return (uint32_t)__cvta_generic_to_shared(p);
}
__device__ __forceinline__ void cpa16u(uint32_t s, const void* g) {
    asm volatile("cp.async.cg.shared.global [%0], [%1], 16;" :: "r"(s), "l"(g));
}
__device__ __forceinline__ void ldsm4(uint32_t& r0, uint32_t& r1, uint32_t& r2,
                                      uint32_t& r3, uint32_t a) {
    asm volatile("ldmatrix.sync.aligned.m8n8.x4.shared.b16 {%0,%1,%2,%3}, [%4];"
                 : "=r"(r0), "=r"(r1), "=r"(r2), "=r"(r3) : "r"(a));
}
__device__ __forceinline__ void mma16(float c[4], const uint32_t a[4], const uint32_t b[2]) {
    asm volatile(
        "mma.sync.aligned.m16n8k16.row.col.f32.f16.f16.f32 "
        "{%0,%1,%2,%3}, {%4,%5,%6,%7}, {%8,%9}, {%0,%1,%2,%3};\n"
        : "+f"(c[0]), "+f"(c[1]), "+f"(c[2]), "+f"(c[3])
        : "r"(a[0]), "r"(a[1]), "r"(a[2]), "r"(a[3]), "r"(b[0]), "r"(b[1]));
}

// SW128 swizzled byte offset within a 128B-row tile (8 x 16B chunks per row)
__device__ __forceinline__ uint32_t swz(int row, int chunk) {
    return (uint32_t)row * 128u + (uint32_t)((chunk ^ (row & 7)) << 4);
}

// load one BK=64 chunk (A, B tiles: 128 rows x 128 bytes) with 128 threads
__device__ __forceinline__ void load_chunk(uint32_t sbase,
    const __half* __restrict__ Ah, const __half* __restrict__ Bh,
    size_t aoff, size_t boff, int k0, int tid)
{
    const int r = tid >> 3;        // 0..15
    const int j = tid & 7;         // 16B chunk within 128B row
    #pragma unroll
    for (int i = 0; i < 8; ++i) {
        int row = r + 16 * i;
        uint32_t so = swz(row, j);
        size_t go = aoff + (size_t)row * GK + k0 + j * 8;
        cpa16u(sbase + OAH + so, Ah + go);
        size_t gob = boff + (size_t)row * GK + k0 + j * 8;
        cpa16u(sbase + OBH + so, Bh + gob);
    }
}

__global__ void __launch_bounds__(NTHR, 2)
gemm_split(int which, float* __restrict__ gout) {
    extern __shared__ char dsm[];
    const uint32_t sb = smem_u32(dsm);
    const int tid  = threadIdx.x;
    const int warp = tid >> 5;
    const int lane = tid & 31;
    const int wm = (warp & 1) * 64;
    const int wn = (warp >> 1) * 64;

    const __half* Ah = g_Ah;
    const __half* Bh = which ? g_Gh : g_Eh;
    const int Ntot = which ? HALFN : DIMN;
    const int nblk = Ntot / BN;
    const int ntiles = (MROWS / BM) * nblk;

    // ldmatrix thread->row mapping; precompute ALL swizzled offsets (per ks)
    const int q = lane >> 3;       // matrix index 0..3
    const int e = lane & 7;        // row within 8
    const int acs = q >> 1;
    const int bcs = q & 1;
    uint32_t aofs[4][4], bofs[4][4];
    #pragma unroll
    for (int ks = 0; ks < 4; ++ks) {
        #pragma unroll
        for (int mt = 0; mt < 4; ++mt) {
            int row = wm + mt * 16 + e + (q & 1) * 8;
            aofs[ks][mt] = OAH + swz(row, 2 * ks + acs);
        }
        #pragma unroll
        for (int p = 0; p < 4; ++p) {
            int row = wn + p * 16 + e + (q >> 1) * 8;
            bofs[ks][p] = OBH + swz(row, 2 * ks + bcs);
        }
    }

    const int g  = lane >> 2;
    const int t4 = lane & 3;
    const int nk = GK / BKC;       // 64

    for (int t = blockIdx.x; t < ntiles; t += gridDim.x) {
        const int mb = t / nblk;
        const int nb = t - mb * nblk;
        const size_t aoff = (size_t)mb * BM * GK;
        const size_t boff = (size_t)nb * BN * GK;

        float acc[4][8][4];
        #pragma unroll
        for (int i = 0; i < 4; ++i)
            #pragma unroll
            for (int jj = 0; jj < 8; ++jj)
                #pragma unroll
                for (int k = 0; k < 4; ++k) acc[i][jj][k] = 0.f;

        // prologue: chunks 0,1 -> stages 0,1
        #pragma unroll
        for (int s = 0; s < 2; ++s) {
            load_chunk(sb + s * STG, Ah, Bh, aoff, boff, s * BKC, tid);
            asm volatile("cp.async.commit_group;" ::: "memory");
        }

        int stage = 0;
        for (int it = 0; it < nk; ++it) {
            if (it + 1 < nk) asm volatile("cp.async.wait_group 1;" ::: "memory");
            else             asm volatile("cp.async.wait_group 0;" ::: "memory");
            __syncthreads();

            if (it + 2 < nk) {
                int ns = stage + 2; if (ns >= STAGES) ns -= STAGES;
                load_chunk(sb + ns * STG, Ah, Bh, aoff, boff,
                           (it + 2) * BKC, tid);
                asm volatile("cp.async.commit_group;" ::: "memory");
            }

            const uint32_t stg = sb + (uint32_t)stage * STG;
            #pragma unroll
            for (int ks = 0; ks < 4; ++ks) {
                uint32_t afh[4][4], bfh[4][4];
                #pragma unroll
                for (int mt = 0; mt < 4; ++mt)
                    ldsm4(afh[mt][0], afh[mt][1], afh[mt][2], afh[mt][3],
                          stg + aofs[ks][mt]);
                #pragma unroll
                for (int p = 0; p < 4; ++p)
                    ldsm4(bfh[p][0], bfh[p][1], bfh[p][2], bfh[p][3],
                          stg + bofs[ks][p]);
                #pragma unroll
                for (int mt = 0; mt < 4; ++mt)
                    #pragma unroll
                    for (int p = 0; p < 4; ++p)
                        #pragma unroll
                        for (int h = 0; h < 2; ++h)
                            mma16(acc[mt][2 * p + h], afh[mt], &bfh[p][2 * h]);
            }
            if (++stage >= STAGES) stage = 0;
        }

        if (which == 0) {
            // GEMM1 epilogue: store W
            #pragma unroll
            for (int mt = 0; mt < 4; ++mt) {
                int row = mb * BM + wm + mt * 16 + g;
                #pragma unroll
                for (int nt = 0; nt < 8; ++nt) {
                    int col = nb * BN + wn + nt * 8 + 2 * t4;
                    float2 v0 = make_float2(acc[mt][nt][0], acc[mt][nt][1]);
                    float2 v1 = make_float2(acc[mt][nt][2], acc[mt][nt][3]);
                    *(float2*)&g_W[(size_t)row * Ntot + col]       = v0;
                    *(float2*)&g_W[(size_t)(row + 8) * Ntot + col] = v1;
                }
            }
        } else {
            // GEMM2 epilogue: fused |.|^2 row reduction -> out[row mod 2048]
            #pragma unroll
            for (int mt = 0; mt < 4; ++mt) {
                float s0 = 0.f, s1 = 0.f;
                #pragma unroll
                for (int nt = 0; nt < 8; ++nt) {
                    s0 += acc[mt][nt][0] * acc[mt][nt][0]
                        + acc[mt][nt][1] * acc[mt][nt][1];
                    s1 += acc[mt][nt][2] * acc[mt][nt][2]
                        + acc[mt][nt][3] * acc[mt][nt][3];
                }
                s0 += __shfl_xor_sync(0xffffffffu, s0, 1);
                s0 += __shfl_xor_sync(0xffffffffu, s0, 2);
                s1 += __shfl_xor_sync(0xffffffffu, s1, 1);
                s1 += __shfl_xor_sync(0xffffffffu, s1, 2);
                if (t4 == 0) {
                    int row = mb * BM + wm + mt * 16 + g;
                    atomicAdd(&gout[row & (NBATCH - 1)], s0);
                    atomicAdd(&gout[(row + 8) & (NBATCH - 1)], s1);
                }
            }
        }
        // protect smem stages from next tile's prologue
        __syncthreads();
    }
}

// ---------------------------------------------------------------------------
// gate sweep: apply 12 complex 2x2 gates per batch row in smem, write fp16
// ---------------------------------------------------------------------------
__global__ __launch_bounds__(256) void gate_kernel() {
    __shared__ float wr[DIMN];
    __shared__ float wi[DIMN];
    const int b = blockIdx.x;
    const float* Wr = g_W + (size_t)b * DIMN;
    const float* Wi = g_W + (size_t)(NBATCH + b) * DIMN;

    for (int j = threadIdx.x * 4; j < DIMN; j += blockDim.x * 4) {
        *(float4*)&wr[j] = *(const float4*)&Wr[j];
        *(float4*)&wi[j] = *(const float4*)&Wi[j];
    }
    __syncthreads();

    #pragma unroll 1
    for (int q = 0; q < NQ; ++q) {
        const float* m = g_gates + q * 8;
        float m00r = m[0], m00i = m[1], m01r = m[2], m01i = m[3];
        float m10r = m[4], m10i = m[5], m11r = m[6], m11i = m[7];
        int p  = NQ - 1 - q;
        int st = 1 << p;
        for (int t = threadIdx.x; t < HALFN; t += blockDim.x) {
            int j0 = ((t >> p) << (p + 1)) | (t & (st - 1));
            int j1 = j0 + st;
            float w0r = wr[j0], w0i = wi[j0];
            float w1r = wr[j1], w1i = wi[j1];
            wr[j0] = m00r * w0r - m00i * w0i + m01r * w1r - m01i * w1i;
            wi[j0] = m00r * w0i + m00i * w0r + m01r * w1i + m01i * w1r;
            wr[j1] = m10r * w0r - m10i * w0i + m11r * w1r - m11i * w1i;
            wi[j1] = m10r * w0i + m10i * w0r + m11r * w1i + m11i * w1r;
        }
        __syncthreads();
    }

    for (int j = threadIdx.x; j < DIMN; j += blockDim.x) {
        g_Ah[(size_t)b * DIMN + j]            = __float2half(wr[j]);
        g_Ah[(size_t)(NBATCH + b) * DIMN + j] = __float2half(wi[j]);
    }
}

// ---------------------------------------------------------------------------
extern "C" void kernel_launch(void* const* d_in, const int* in_sizes, int n_in,
                              void* d_out, int out_size) {
    const float* inputs = (const float*)d_in[0];   // [2048,12]
    const float* weight = (const float*)d_in[1];   // [27]
    const float* E      = (const float*)d_in[2];   // [4096,4096]
    float* out          = (float*)d_out;           // [2048]

    cudaFuncSetAttribute(gemm_split, cudaFuncAttributeMaxDynamicSharedMemorySize,
                         DSMEM);
    int nsm = 148;
    cudaDeviceGetAttribute(&nsm, cudaDevAttrMultiProcessorCount, 0);
    const int pgrid = 2 * nsm;     // persistent grid: 2 CTAs per SM

    cudaMemsetAsync(out, 0, (size_t)out_size * sizeof(float));
    prep_kernel<<<1, 32>>>(weight);
    split_EG<<<(HALFN * DIMN / 4) / 256, 256>>>(E, weight);
    encode_kernel<<<NBATCH, 256>>>(inputs);

    gemm_split<<<pgrid, NTHR, DSMEM>>>(0, out);
    gate_kernel<<<NBATCH, 256>>>();
    gemm_split<<<pgrid, NTHR, DSMEM>>>(1, out);
}